// round 7
// baseline (speedup 1.0000x reference)
#include <cuda_runtime.h>
#include <cstdint>

#define NN 50000
#define EE 800000
#define FIN 500
#define HH 64
#define CO 16
#define SCAN_T 1024
#define SCAN_CH 49   // ceil(NN/1024)

// ---------------- scratch (device globals; allocation-free) ----------------
__device__ float g_xw_a[NN * HH];
__device__ float g_xw_b[NN * HH];
__device__ float g_h[NN * 2 * HH];
__device__ float g_xw_l[NN * CO];
__device__ int   g_degi_st[NN], g_degi_ts[NN];
__device__ int   g_rowstart[NN + 1];
__device__ int   g_cursor[NN];
__device__ int   g_src_sorted[EE];
__device__ float g_cdir_sorted[EE];   // sign encodes branch: + => st (xw_a), - => ts (xw_b)
__device__ float g_call_sorted[EE];
__device__ float g_dinv_st[NN], g_dinv_ts[NN], g_dinv_all[NN];
__device__ int   g_flags[2];          // [0]=saw_float_bits, [1]=saw_byte_layout

// ---------------- helpers ----------------
__device__ __forceinline__ int edge_reversed(const void* m, int e) {
    if (g_flags[1]) return ((const unsigned char*)m)[e] != 0;
    if (g_flags[0]) return ((const float*)m)[e] != 0.0f;
    return ((const int*)m)[e] != 0;
}

// ---------------- prep: zero degree arrays + probe is_reversed layout ----------------
// Probe scans 200000 words: float32/int32 layouts have 800000 words; uint8 has 200000.
__global__ void k_prep(const unsigned int* __restrict__ m) {
    int i = blockIdx.x * blockDim.x + threadIdx.x;
    if (i < NN) { g_degi_st[i] = 0; g_degi_ts[i] = 0; }
    if (i < 2) g_flags[i] = 0;
    unsigned int sawF = 0, sawB = 0;
    if (i < 200000) {
        unsigned int w = m[i];
        if (w > 1u) { if (w == 0x3F800000u) sawF = 1; else sawB = 1; }
    }
    sawF = __any_sync(0xFFFFFFFF, sawF);
    sawB = __any_sync(0xFFFFFFFF, sawB);
    if ((threadIdx.x & 31) == 0) {
        if (sawF) atomicOr(&g_flags[0], 1);
        if (sawB) atomicOr(&g_flags[1], 1);
    }
}

// ---------------- degree histogram (int atomics) ----------------
__global__ void k_hist(const int* __restrict__ dst, const void* __restrict__ mrev) {
    int e = blockIdx.x * blockDim.x + threadIdx.x;
    if (e >= EE) return;
    int d = dst[e];
    if (edge_reversed(mrev, e)) atomicAdd(&g_degi_ts[d], 1);
    else                        atomicAdd(&g_degi_st[d], 1);
}

__global__ void k_dinv() {
    int n = blockIdx.x * blockDim.x + threadIdx.x;
    if (n >= NN) return;
    float ds = (float)g_degi_st[n], dt = (float)g_degi_ts[n];
    g_dinv_st[n]  = rsqrtf(ds + 1.f);
    g_dinv_ts[n]  = rsqrtf(dt + 1.f);
    g_dinv_all[n] = rsqrtf(ds + dt + 1.f);
}

// ---------------- exclusive scan of total degree -> rowstart + cursor ----------------
__global__ void k_scan() {
    int t = threadIdx.x;
    int begin = t * SCAN_CH;
    int end = begin + SCAN_CH; if (end > NN) end = NN;
    int local = 0;
    for (int i = begin; i < end; i++) local += g_degi_st[i] + g_degi_ts[i];

    int lane = t & 31, wid = t >> 5;
    int v = local;
#pragma unroll
    for (int o = 1; o < 32; o <<= 1) {
        int u = __shfl_up_sync(0xFFFFFFFF, v, o);
        if (lane >= o) v += u;
    }
    __shared__ int ws[32];
    if (lane == 31) ws[wid] = v;
    __syncthreads();
    if (wid == 0) {
        int s = ws[lane];
#pragma unroll
        for (int o = 1; o < 32; o <<= 1) {
            int u = __shfl_up_sync(0xFFFFFFFF, s, o);
            if (lane >= o) s += u;
        }
        ws[lane] = s;
    }
    __syncthreads();
    int excl = v - local + (wid > 0 ? ws[wid - 1] : 0);
    int run = excl;
    for (int i = begin; i < end; i++) {
        g_rowstart[i] = run;
        g_cursor[i] = run;           // cursor doubles as write pointer
        run += g_degi_st[i] + g_degi_ts[i];
    }
    if (t == SCAN_T - 1) g_rowstart[NN] = run;   // == EE
}

// ---------------- fill CSR buckets with src + coefficients ----------------
__global__ void k_fill(const int* __restrict__ src, const int* __restrict__ dst,
                       const void* __restrict__ mrev) {
    int e = blockIdx.x * blockDim.x + threadIdx.x;
    if (e >= EE) return;
    int s = src[e], d = dst[e];
    int rev = edge_reversed(mrev, e);
    int pos = atomicAdd(&g_cursor[d], 1);
    float c = rev ? (g_dinv_ts[s] * g_dinv_ts[d]) : (g_dinv_st[s] * g_dinv_st[d]);
    g_src_sorted[pos]  = s;
    g_cdir_sorted[pos] = rev ? -c : c;
    g_call_sorted[pos] = g_dinv_all[s] * g_dinv_all[d];
}

// ---------------- GEMM: C[M,128] = A[M,K] @ [Wa | Wb], double-buffered ----------------
__global__ __launch_bounds__(256, 2)
void k_gemm128(const float* __restrict__ Aparam, int M, int K,
               const float* __restrict__ Wa, const float* __restrict__ Wb,
               int asel) {
    const float* A = asel ? g_h : Aparam;
    __shared__ float As[2][8 * 128];
    __shared__ float Bs[2][8 * 128];
    int tid = threadIdx.x;
    int r0 = (tid >> 4) * 8;
    int c0 = (tid & 15) * 8;
    int bm = blockIdx.x * 128;

    int arow  = tid >> 1;         // 0..127
    int akoff = (tid & 1) * 4;    // 0 or 4
    int bkk   = tid >> 5;         // 0..7
    int bc    = (tid & 31) * 4;   // 0..124

    int grow = bm + arow;
    const float* Abase = A + (size_t)grow * K + akoff;
    bool arow_ok = grow < M;

    float acc[8][8];
#pragma unroll
    for (int i = 0; i < 8; i++)
#pragma unroll
        for (int j = 0; j < 8; j++) acc[i][j] = 0.f;

    // prologue: load tile 0 into regs, store to buf 0
    float4 av = make_float4(0.f, 0.f, 0.f, 0.f);
    if (arow_ok && akoff < K) av = *(const float4*)(Abase);
    float4 bv = make_float4(0.f, 0.f, 0.f, 0.f);
    if (bkk < K) {
        if (bc < 64) bv = *(const float4*)(Wa + bkk * 64 + bc);
        else         bv = *(const float4*)(Wb + bkk * 64 + (bc - 64));
    }
    As[0][(akoff + 0) * 128 + arow] = av.x;
    As[0][(akoff + 1) * 128 + arow] = av.y;
    As[0][(akoff + 2) * 128 + arow] = av.z;
    As[0][(akoff + 3) * 128 + arow] = av.w;
    *(float4*)&Bs[0][bkk * 128 + bc] = bv;
    __syncthreads();

    int buf = 0;
    for (int k0 = 0; k0 < K; k0 += 8) {
        int kn = k0 + 8;
        float4 av2 = make_float4(0.f, 0.f, 0.f, 0.f);
        float4 bv2 = make_float4(0.f, 0.f, 0.f, 0.f);
        if (kn < K) {
            int gk = kn + akoff;
            if (arow_ok && gk < K) av2 = *(const float4*)(Abase + kn);
            int bk = kn + bkk;
            if (bk < K) {
                if (bc < 64) bv2 = *(const float4*)(Wa + bk * 64 + bc);
                else         bv2 = *(const float4*)(Wb + bk * 64 + (bc - 64));
            }
        }

#pragma unroll
        for (int kk = 0; kk < 8; kk++) {
            float4 a0 = *(const float4*)&As[buf][kk * 128 + r0];
            float4 a1 = *(const float4*)&As[buf][kk * 128 + r0 + 4];
            float4 b0 = *(const float4*)&Bs[buf][kk * 128 + c0];
            float4 b1 = *(const float4*)&Bs[buf][kk * 128 + c0 + 4];
            float ar[8] = {a0.x, a0.y, a0.z, a0.w, a1.x, a1.y, a1.z, a1.w};
            float br[8] = {b0.x, b0.y, b0.z, b0.w, b1.x, b1.y, b1.z, b1.w};
#pragma unroll
            for (int i = 0; i < 8; i++)
#pragma unroll
                for (int j = 0; j < 8; j++)
                    acc[i][j] = fmaf(ar[i], br[j], acc[i][j]);
        }

        if (kn < K) {
            int nb = buf ^ 1;
            As[nb][(akoff + 0) * 128 + arow] = av2.x;
            As[nb][(akoff + 1) * 128 + arow] = av2.y;
            As[nb][(akoff + 2) * 128 + arow] = av2.z;
            As[nb][(akoff + 3) * 128 + arow] = av2.w;
            *(float4*)&Bs[nb][bkk * 128 + bc] = bv2;
            __syncthreads();
            buf = nb;
        }
    }

    float* C = (c0 < 64) ? g_xw_a : g_xw_b;
    int ccol = (c0 < 64) ? c0 : c0 - 64;
#pragma unroll
    for (int i = 0; i < 8; i++) {
        int row = bm + r0 + i;
        if (row < M) {
            *(float4*)(C + (size_t)row * 64 + ccol)     = make_float4(acc[i][0], acc[i][1], acc[i][2], acc[i][3]);
            *(float4*)(C + (size_t)row * 64 + ccol + 4) = make_float4(acc[i][4], acc[i][5], acc[i][6], acc[i][7]);
        }
    }
}

// ---------------- gather aggregation (both branches) + combine + relu -> h ----------------
// block = node, 64 threads = channels. No atomics. 4-way ILP.
__global__ __launch_bounds__(64)
void k_gather64(const float* __restrict__ b_st, const float* __restrict__ b_ts) {
    int n = blockIdx.x;
    int c = threadIdx.x;
    int rs = g_rowstart[n], re = g_rowstart[n + 1];
    float acc_a = 0.f, acc_b = 0.f;
    int i = rs;
    for (; i + 3 < re; i += 4) {
        int   s0 = g_src_sorted[i],   s1 = g_src_sorted[i+1];
        int   s2 = g_src_sorted[i+2], s3 = g_src_sorted[i+3];
        float c0 = g_cdir_sorted[i],   c1 = g_cdir_sorted[i+1];
        float c2 = g_cdir_sorted[i+2], c3 = g_cdir_sorted[i+3];
        float v0 = (c0 >= 0.f) ? g_xw_a[s0 * 64 + c] : g_xw_b[s0 * 64 + c];
        float v1 = (c1 >= 0.f) ? g_xw_a[s1 * 64 + c] : g_xw_b[s1 * 64 + c];
        float v2 = (c2 >= 0.f) ? g_xw_a[s2 * 64 + c] : g_xw_b[s2 * 64 + c];
        float v3 = (c3 >= 0.f) ? g_xw_a[s3 * 64 + c] : g_xw_b[s3 * 64 + c];
        if (c0 >= 0.f) acc_a = fmaf(c0, v0, acc_a); else acc_b = fmaf(-c0, v0, acc_b);
        if (c1 >= 0.f) acc_a = fmaf(c1, v1, acc_a); else acc_b = fmaf(-c1, v1, acc_b);
        if (c2 >= 0.f) acc_a = fmaf(c2, v2, acc_a); else acc_b = fmaf(-c2, v2, acc_b);
        if (c3 >= 0.f) acc_a = fmaf(c3, v3, acc_a); else acc_b = fmaf(-c3, v3, acc_b);
    }
    for (; i < re; i++) {
        int   s0 = g_src_sorted[i];
        float c0 = g_cdir_sorted[i];
        float v0 = (c0 >= 0.f) ? g_xw_a[s0 * 64 + c] : g_xw_b[s0 * 64 + c];
        if (c0 >= 0.f) acc_a = fmaf(c0, v0, acc_a); else acc_b = fmaf(-c0, v0, acc_b);
    }
    float da = g_dinv_st[n], db = g_dinv_ts[n];
    float va = acc_a + g_xw_a[n * 64 + c] * da * da + b_st[c];
    float vb = acc_b + g_xw_b[n * 64 + c] * db * db + b_ts[c];
    g_h[n * 128 + c]      = fmaxf(va, 0.f);
    g_h[n * 128 + 64 + c] = fmaxf(vb, 0.f);
}

// ---------------- last layer: xw_l = h @ W_last ----------------
__global__ void k_gemm16(const float* __restrict__ Wl) {
    __shared__ float Ws[128 * 16];
    for (int i = threadIdx.x; i < 128 * 16; i += blockDim.x) Ws[i] = Wl[i];
    __syncthreads();
    int idx = blockIdx.x * blockDim.x + threadIdx.x;
    int n = idx >> 4;
    int j = idx & 15;
    if (n >= NN) return;
    const float* hr = g_h + (size_t)n * 128;
    float acc = 0.f;
#pragma unroll
    for (int k = 0; k < 128; k++) acc = fmaf(hr[k], Ws[k * 16 + j], acc);
    g_xw_l[n * 16 + j] = acc;
}

// ---------------- final gather + combine + log_softmax -> out ----------------
// 128 threads = 8 nodes x 16 lanes. NN % 8 == 0 so no partial blocks.
__global__ __launch_bounds__(128)
void k_gather16_final(const float* __restrict__ b_last, float* __restrict__ out) {
    int lid = threadIdx.x & 15;
    int grp = threadIdx.x >> 4;
    int n = blockIdx.x * 8 + grp;
    int rs = g_rowstart[n], re = g_rowstart[n + 1];
    float acc = 0.f;
    int i = rs;
    for (; i + 1 < re; i += 2) {
        int   s0 = g_src_sorted[i],  s1 = g_src_sorted[i+1];
        float f0 = g_call_sorted[i], f1 = g_call_sorted[i+1];
        acc = fmaf(f0, g_xw_l[s0 * 16 + lid], acc);
        acc = fmaf(f1, g_xw_l[s1 * 16 + lid], acc);
    }
    if (i < re) acc = fmaf(g_call_sorted[i], g_xw_l[g_src_sorted[i] * 16 + lid], acc);
    float dinv = g_dinv_all[n];
    float v = acc + g_xw_l[n * 16 + lid] * dinv * dinv + b_last[lid];
    float m = v;
#pragma unroll
    for (int o = 8; o > 0; o >>= 1) m = fmaxf(m, __shfl_xor_sync(0xFFFFFFFF, m, o, 16));
    float ex = expf(v - m);
    float ssum = ex;
#pragma unroll
    for (int o = 8; o > 0; o >>= 1) ssum += __shfl_xor_sync(0xFFFFFFFF, ssum, o, 16);
    out[n * 16 + lid] = v - (logf(ssum) + m);
}

// ---------------- launch ----------------
extern "C" void kernel_launch(void* const* d_in, const int* in_sizes, int n_in,
                              void* d_out, int out_size) {
    const float* x      = (const float*)d_in[0];
    const int*   ei     = (const int*)d_in[1];
    const void*  mrev   = d_in[2];
    const float* W_st0  = (const float*)d_in[3];
    const float* b_st0  = (const float*)d_in[4];
    const float* W_ts0  = (const float*)d_in[5];
    const float* b_ts0  = (const float*)d_in[6];
    const float* W_st1  = (const float*)d_in[7];
    const float* b_st1  = (const float*)d_in[8];
    const float* W_ts1  = (const float*)d_in[9];
    const float* b_ts1  = (const float*)d_in[10];
    const float* W_last = (const float*)d_in[11];
    const float* b_last = (const float*)d_in[12];
    float* out = (float*)d_out;

    const int* srcp = ei;
    const int* dstp = ei + EE;
    const int TB = 256;

    // CSR build + normalization (launches 0-4)
    k_prep<<<(200000 + TB - 1) / TB, TB>>>((const unsigned int*)mrev);
    k_hist<<<(EE + TB - 1) / TB, TB>>>(dstp, mrev);
    k_dinv<<<(NN + TB - 1) / TB, TB>>>();
    k_scan<<<1, SCAN_T>>>();
    k_fill<<<(EE + TB - 1) / TB, TB>>>(srcp, dstp, mrev);

    const int GEMM_BLOCKS = (NN + 127) / 128;

    // layer 0 (gemm128 is launch #5 -> profiled by ncu -s 5 -c 1)
    k_gemm128<<<GEMM_BLOCKS, 256>>>(x, NN, FIN, W_st0, W_ts0, 0);
    k_gather64<<<NN, 64>>>(b_st0, b_ts0);

    // layer 1
    k_gemm128<<<GEMM_BLOCKS, 256>>>(nullptr, NN, 2 * HH, W_st1, W_ts1, 1);
    k_gather64<<<NN, 64>>>(b_st1, b_ts1);

    // last layer
    k_gemm16<<<(NN * 16) / TB, TB>>>(W_last);
    k_gather16_final<<<NN / 8, 128>>>(b_last, out);
}

// round 8
// speedup vs baseline: 1.2361x; 1.2361x over previous
#include <cuda_runtime.h>
#include <cstdint>

#define NN 50000
#define EE 800000
#define FIN 500
#define HH 64
#define CO 16
#define SCAN_B 49    // ceil(NN/1024)

// ---------------- scratch (device globals; allocation-free) ----------------
__device__ float g_xw_a[NN * HH];
__device__ float g_xw_b[NN * HH];
__device__ float g_h[NN * 2 * HH];
__device__ float g_xw_l[NN * CO];
__device__ int   g_degi_st[NN], g_degi_ts[NN];
__device__ int   g_degtot[NN];
__device__ int   g_rowstart[NN + 1];
__device__ int   g_cursor[NN];
__device__ int   g_bsum[SCAN_B];
__device__ int   g_boff[SCAN_B];
__device__ int   g_src_sorted[EE];
__device__ float g_cdir_sorted[EE];   // sign encodes branch: + => st (xw_a), - => ts (xw_b)
__device__ float g_call_sorted[EE];
__device__ float g_dinv_st[NN], g_dinv_ts[NN], g_dinv_all[NN];
__device__ int   g_flags[2];          // [0]=saw_float_bits, [1]=saw_byte_layout

// ---------------- helpers ----------------
__device__ __forceinline__ int edge_reversed(const void* m, int e) {
    if (g_flags[1]) return ((const unsigned char*)m)[e] != 0;
    if (g_flags[0]) return ((const float*)m)[e] != 0.0f;
    return ((const int*)m)[e] != 0;
}

// ---------------- prep: zero degree arrays + probe is_reversed layout ----------------
// Probe scans 200000 words: float32/int32 layouts have 800000 words; uint8 has 200000.
__global__ void k_prep(const unsigned int* __restrict__ m) {
    int i = blockIdx.x * blockDim.x + threadIdx.x;
    if (i < NN) { g_degi_st[i] = 0; g_degi_ts[i] = 0; }
    if (i < 2) g_flags[i] = 0;
    unsigned int sawF = 0, sawB = 0;
    if (i < 200000) {
        unsigned int w = m[i];
        if (w > 1u) { if (w == 0x3F800000u) sawF = 1; else sawB = 1; }
    }
    sawF = __any_sync(0xFFFFFFFF, sawF);
    sawB = __any_sync(0xFFFFFFFF, sawB);
    if ((threadIdx.x & 31) == 0) {
        if (sawF) atomicOr(&g_flags[0], 1);
        if (sawB) atomicOr(&g_flags[1], 1);
    }
}

// ---------------- degree histogram (int atomics) ----------------
__global__ void k_hist(const int* __restrict__ dst, const void* __restrict__ mrev) {
    int e = blockIdx.x * blockDim.x + threadIdx.x;
    if (e >= EE) return;
    int d = dst[e];
    if (edge_reversed(mrev, e)) atomicAdd(&g_degi_ts[d], 1);
    else                        atomicAdd(&g_degi_st[d], 1);
}

__global__ void k_dinv() {
    int n = blockIdx.x * blockDim.x + threadIdx.x;
    if (n >= NN) return;
    int ids = g_degi_st[n], idt = g_degi_ts[n];
    float ds = (float)ids, dt = (float)idt;
    g_degtot[n] = ids + idt;
    g_dinv_st[n]  = rsqrtf(ds + 1.f);
    g_dinv_ts[n]  = rsqrtf(dt + 1.f);
    g_dinv_all[n] = rsqrtf(ds + dt + 1.f);
}

// ---------------- two-level exclusive scan of degtot -> rowstart ----------------
// scan1: per-block (1024 elems) exclusive scan, block sums out
__global__ __launch_bounds__(1024)
void k_scan1() {
    int b = blockIdx.x, t = threadIdx.x;
    int i = b * 1024 + t;
    int v = (i < NN) ? g_degtot[i] : 0;
    int lane = t & 31, wid = t >> 5;
    int x = v;
#pragma unroll
    for (int o = 1; o < 32; o <<= 1) {
        int u = __shfl_up_sync(0xFFFFFFFF, x, o);
        if (lane >= o) x += u;
    }
    __shared__ int ws[32];
    if (lane == 31) ws[wid] = x;
    __syncthreads();
    if (wid == 0) {
        int s = ws[lane];
#pragma unroll
        for (int o = 1; o < 32; o <<= 1) {
            int u = __shfl_up_sync(0xFFFFFFFF, s, o);
            if (lane >= o) s += u;
        }
        ws[lane] = s;
    }
    __syncthreads();
    int incl = x + (wid > 0 ? ws[wid - 1] : 0);
    if (i < NN) g_rowstart[i] = incl - v;     // exclusive, no block offset yet
    if (t == 1023) g_bsum[b] = incl;          // block total
}

// scan2: one block of 64 threads scans 49 block sums -> g_boff (exclusive)
__global__ __launch_bounds__(64)
void k_scan2() {
    int t = threadIdx.x;
    int v = (t < SCAN_B) ? g_bsum[t] : 0;
    int lane = t & 31, wid = t >> 5;
    int x = v;
#pragma unroll
    for (int o = 1; o < 32; o <<= 1) {
        int u = __shfl_up_sync(0xFFFFFFFF, x, o);
        if (lane >= o) x += u;
    }
    __shared__ int w0;
    if (wid == 0 && lane == 31) w0 = x;
    __syncthreads();
    int incl = x + (wid == 1 ? w0 : 0);
    if (t < SCAN_B) g_boff[t] = incl - v;     // exclusive
}

// scan3: add block offsets; init cursor; rowstart[NN] = EE (sum of degrees == E)
__global__ __launch_bounds__(1024)
void k_scan3() {
    int b = blockIdx.x, t = threadIdx.x;
    int i = b * 1024 + t;
    if (i < NN) {
        int r = g_rowstart[i] + g_boff[b];
        g_rowstart[i] = r;
        g_cursor[i] = r;
    }
    if (i == 0) g_rowstart[NN] = EE;
}

// ---------------- fill CSR buckets with src + coefficients ----------------
__global__ void k_fill(const int* __restrict__ src, const int* __restrict__ dst,
                       const void* __restrict__ mrev) {
    int e = blockIdx.x * blockDim.x + threadIdx.x;
    if (e >= EE) return;
    int s = src[e], d = dst[e];
    int rev = edge_reversed(mrev, e);
    int pos = atomicAdd(&g_cursor[d], 1);
    float c = rev ? (g_dinv_ts[s] * g_dinv_ts[d]) : (g_dinv_st[s] * g_dinv_st[d]);
    g_src_sorted[pos]  = s;
    g_cdir_sorted[pos] = rev ? -c : c;
    g_call_sorted[pos] = g_dinv_all[s] * g_dinv_all[d];
}

// ---------------- GEMM: C[M,128] = A[M,K] @ [Wa | Wb], double-buffered ----------------
__global__ __launch_bounds__(256, 2)
void k_gemm128(const float* __restrict__ Aparam, int M, int K,
               const float* __restrict__ Wa, const float* __restrict__ Wb,
               int asel) {
    const float* A = asel ? g_h : Aparam;
    __shared__ float As[2][8 * 128];
    __shared__ float Bs[2][8 * 128];
    int tid = threadIdx.x;
    int r0 = (tid >> 4) * 8;
    int c0 = (tid & 15) * 8;
    int bm = blockIdx.x * 128;

    int arow  = tid >> 1;         // 0..127
    int akoff = (tid & 1) * 4;    // 0 or 4
    int bkk   = tid >> 5;         // 0..7
    int bc    = (tid & 31) * 4;   // 0..124

    int grow = bm + arow;
    const float* Abase = A + (size_t)grow * K + akoff;
    bool arow_ok = grow < M;

    float acc[8][8];
#pragma unroll
    for (int i = 0; i < 8; i++)
#pragma unroll
        for (int j = 0; j < 8; j++) acc[i][j] = 0.f;

    float4 av = make_float4(0.f, 0.f, 0.f, 0.f);
    if (arow_ok && akoff < K) av = *(const float4*)(Abase);
    float4 bv = make_float4(0.f, 0.f, 0.f, 0.f);
    if (bkk < K) {
        if (bc < 64) bv = *(const float4*)(Wa + bkk * 64 + bc);
        else         bv = *(const float4*)(Wb + bkk * 64 + (bc - 64));
    }
    As[0][(akoff + 0) * 128 + arow] = av.x;
    As[0][(akoff + 1) * 128 + arow] = av.y;
    As[0][(akoff + 2) * 128 + arow] = av.z;
    As[0][(akoff + 3) * 128 + arow] = av.w;
    *(float4*)&Bs[0][bkk * 128 + bc] = bv;
    __syncthreads();

    int buf = 0;
    for (int k0 = 0; k0 < K; k0 += 8) {
        int kn = k0 + 8;
        float4 av2 = make_float4(0.f, 0.f, 0.f, 0.f);
        float4 bv2 = make_float4(0.f, 0.f, 0.f, 0.f);
        if (kn < K) {
            int gk = kn + akoff;
            if (arow_ok && gk < K) av2 = *(const float4*)(Abase + kn);
            int bk = kn + bkk;
            if (bk < K) {
                if (bc < 64) bv2 = *(const float4*)(Wa + bk * 64 + bc);
                else         bv2 = *(const float4*)(Wb + bk * 64 + (bc - 64));
            }
        }

#pragma unroll
        for (int kk = 0; kk < 8; kk++) {
            float4 a0 = *(const float4*)&As[buf][kk * 128 + r0];
            float4 a1 = *(const float4*)&As[buf][kk * 128 + r0 + 4];
            float4 b0 = *(const float4*)&Bs[buf][kk * 128 + c0];
            float4 b1 = *(const float4*)&Bs[buf][kk * 128 + c0 + 4];
            float ar[8] = {a0.x, a0.y, a0.z, a0.w, a1.x, a1.y, a1.z, a1.w};
            float br[8] = {b0.x, b0.y, b0.z, b0.w, b1.x, b1.y, b1.z, b1.w};
#pragma unroll
            for (int i = 0; i < 8; i++)
#pragma unroll
                for (int j = 0; j < 8; j++)
                    acc[i][j] = fmaf(ar[i], br[j], acc[i][j]);
        }

        if (kn < K) {
            int nb = buf ^ 1;
            As[nb][(akoff + 0) * 128 + arow] = av2.x;
            As[nb][(akoff + 1) * 128 + arow] = av2.y;
            As[nb][(akoff + 2) * 128 + arow] = av2.z;
            As[nb][(akoff + 3) * 128 + arow] = av2.w;
            *(float4*)&Bs[nb][bkk * 128 + bc] = bv2;
            __syncthreads();
            buf = nb;
        }
    }

    float* C = (c0 < 64) ? g_xw_a : g_xw_b;
    int ccol = (c0 < 64) ? c0 : c0 - 64;
#pragma unroll
    for (int i = 0; i < 8; i++) {
        int row = bm + r0 + i;
        if (row < M) {
            *(float4*)(C + (size_t)row * 64 + ccol)     = make_float4(acc[i][0], acc[i][1], acc[i][2], acc[i][3]);
            *(float4*)(C + (size_t)row * 64 + ccol + 4) = make_float4(acc[i][4], acc[i][5], acc[i][6], acc[i][7]);
        }
    }
}

// ---------------- gather aggregation (both branches) + combine + relu -> h ----------------
__global__ __launch_bounds__(64)
void k_gather64(const float* __restrict__ b_st, const float* __restrict__ b_ts) {
    int n = blockIdx.x;
    int c = threadIdx.x;
    int rs = g_rowstart[n], re = g_rowstart[n + 1];
    float acc_a = 0.f, acc_b = 0.f;
    int i = rs;
    for (; i + 3 < re; i += 4) {
        int   s0 = g_src_sorted[i],   s1 = g_src_sorted[i+1];
        int   s2 = g_src_sorted[i+2], s3 = g_src_sorted[i+3];
        float c0 = g_cdir_sorted[i],   c1 = g_cdir_sorted[i+1];
        float c2 = g_cdir_sorted[i+2], c3 = g_cdir_sorted[i+3];
        float v0 = (c0 >= 0.f) ? g_xw_a[s0 * 64 + c] : g_xw_b[s0 * 64 + c];
        float v1 = (c1 >= 0.f) ? g_xw_a[s1 * 64 + c] : g_xw_b[s1 * 64 + c];
        float v2 = (c2 >= 0.f) ? g_xw_a[s2 * 64 + c] : g_xw_b[s2 * 64 + c];
        float v3 = (c3 >= 0.f) ? g_xw_a[s3 * 64 + c] : g_xw_b[s3 * 64 + c];
        if (c0 >= 0.f) acc_a = fmaf(c0, v0, acc_a); else acc_b = fmaf(-c0, v0, acc_b);
        if (c1 >= 0.f) acc_a = fmaf(c1, v1, acc_a); else acc_b = fmaf(-c1, v1, acc_b);
        if (c2 >= 0.f) acc_a = fmaf(c2, v2, acc_a); else acc_b = fmaf(-c2, v2, acc_b);
        if (c3 >= 0.f) acc_a = fmaf(c3, v3, acc_a); else acc_b = fmaf(-c3, v3, acc_b);
    }
    for (; i < re; i++) {
        int   s0 = g_src_sorted[i];
        float c0 = g_cdir_sorted[i];
        float v0 = (c0 >= 0.f) ? g_xw_a[s0 * 64 + c] : g_xw_b[s0 * 64 + c];
        if (c0 >= 0.f) acc_a = fmaf(c0, v0, acc_a); else acc_b = fmaf(-c0, v0, acc_b);
    }
    float da = g_dinv_st[n], db = g_dinv_ts[n];
    float va = acc_a + g_xw_a[n * 64 + c] * da * da + b_st[c];
    float vb = acc_b + g_xw_b[n * 64 + c] * db * db + b_ts[c];
    g_h[n * 128 + c]      = fmaxf(va, 0.f);
    g_h[n * 128 + 64 + c] = fmaxf(vb, 0.f);
}

// ---------------- last layer: xw_l = h @ W_last ----------------
__global__ void k_gemm16(const float* __restrict__ Wl) {
    __shared__ float Ws[128 * 16];
    for (int i = threadIdx.x; i < 128 * 16; i += blockDim.x) Ws[i] = Wl[i];
    __syncthreads();
    int idx = blockIdx.x * blockDim.x + threadIdx.x;
    int n = idx >> 4;
    int j = idx & 15;
    if (n >= NN) return;
    const float* hr = g_h + (size_t)n * 128;
    float acc = 0.f;
#pragma unroll
    for (int k = 0; k < 128; k++) acc = fmaf(hr[k], Ws[k * 16 + j], acc);
    g_xw_l[n * 16 + j] = acc;
}

// ---------------- final gather + combine + log_softmax -> out ----------------
__global__ __launch_bounds__(128)
void k_gather16_final(const float* __restrict__ b_last, float* __restrict__ out) {
    int lid = threadIdx.x & 15;
    int grp = threadIdx.x >> 4;
    int n = blockIdx.x * 8 + grp;
    int rs = g_rowstart[n], re = g_rowstart[n + 1];
    float acc = 0.f;
    int i = rs;
    for (; i + 1 < re; i += 2) {
        int   s0 = g_src_sorted[i],  s1 = g_src_sorted[i+1];
        float f0 = g_call_sorted[i], f1 = g_call_sorted[i+1];
        acc = fmaf(f0, g_xw_l[s0 * 16 + lid], acc);
        acc = fmaf(f1, g_xw_l[s1 * 16 + lid], acc);
    }
    if (i < re) acc = fmaf(g_call_sorted[i], g_xw_l[g_src_sorted[i] * 16 + lid], acc);
    float dinv = g_dinv_all[n];
    float v = acc + g_xw_l[n * 16 + lid] * dinv * dinv + b_last[lid];
    float m = v;
#pragma unroll
    for (int o = 8; o > 0; o >>= 1) m = fmaxf(m, __shfl_xor_sync(0xFFFFFFFF, m, o, 16));
    float ex = expf(v - m);
    float ssum = ex;
#pragma unroll
    for (int o = 8; o > 0; o >>= 1) ssum += __shfl_xor_sync(0xFFFFFFFF, ssum, o, 16);
    out[n * 16 + lid] = v - (logf(ssum) + m);
}

// ---------------- launch ----------------
extern "C" void kernel_launch(void* const* d_in, const int* in_sizes, int n_in,
                              void* d_out, int out_size) {
    const float* x      = (const float*)d_in[0];
    const int*   ei     = (const int*)d_in[1];
    const void*  mrev   = d_in[2];
    const float* W_st0  = (const float*)d_in[3];
    const float* b_st0  = (const float*)d_in[4];
    const float* W_ts0  = (const float*)d_in[5];
    const float* b_ts0  = (const float*)d_in[6];
    const float* W_st1  = (const float*)d_in[7];
    const float* b_st1  = (const float*)d_in[8];
    const float* W_ts1  = (const float*)d_in[9];
    const float* b_ts1  = (const float*)d_in[10];
    const float* W_last = (const float*)d_in[11];
    const float* b_last = (const float*)d_in[12];
    float* out = (float*)d_out;

    const int* srcp = ei;
    const int* dstp = ei + EE;
    const int TB = 256;
    const int GEMM_BLOCKS = (NN + 127) / 128;

    // launches 0-2: prep / hist / dinv
    k_prep<<<(200000 + TB - 1) / TB, TB>>>((const unsigned int*)mrev);
    k_hist<<<(EE + TB - 1) / TB, TB>>>(dstp, mrev);
    k_dinv<<<(NN + TB - 1) / TB, TB>>>();

    // launch 3: gemm128 L0 (profiled slot; independent of CSR build)
    k_gemm128<<<GEMM_BLOCKS, 256>>>(x, NN, FIN, W_st0, W_ts0, 0);

    // CSR build (parallel two-level scan + fill)
    k_scan1<<<SCAN_B, 1024>>>();
    k_scan2<<<1, 64>>>();
    k_scan3<<<SCAN_B, 1024>>>();
    k_fill<<<(EE + TB - 1) / TB, TB>>>(srcp, dstp, mrev);

    // layer 0 aggregation
    k_gather64<<<NN, 64>>>(b_st0, b_ts0);

    // layer 1
    k_gemm128<<<GEMM_BLOCKS, 256>>>(nullptr, NN, 2 * HH, W_st1, W_ts1, 1);
    k_gather64<<<NN, 64>>>(b_st1, b_ts1);

    // last layer
    k_gemm16<<<(NN * 16) / TB, TB>>>(W_last);
    k_gather16_final<<<NN / 8, 128>>>(b_last, out);
}

// round 9
// speedup vs baseline: 1.6116x; 1.3038x over previous
#include <cuda_runtime.h>
#include <cstdint>

#define NN 50000
#define EE 800000
#define FIN 500
#define HH 64
#define CO 16
#define SCAN_B 49    // ceil(NN/1024)
#define BSTRIDE 136  // B smem row stride in floats (136 mod 32 == 8 -> conflict-free frags)

// ---------------- scratch (device globals; allocation-free) ----------------
__device__ float g_xw_a[NN * HH];
__device__ float g_xw_b[NN * HH];
__device__ float g_h[NN * 2 * HH];
__device__ float g_xw_l[NN * CO];
__device__ int   g_degi_st[NN], g_degi_ts[NN];
__device__ int   g_degtot[NN];
__device__ int   g_rowstart[NN + 1];
__device__ int   g_cursor[NN];
__device__ int   g_bsum[SCAN_B];
__device__ int   g_boff[SCAN_B];
__device__ int   g_src_sorted[EE];
__device__ float g_cdir_sorted[EE];   // sign encodes branch: + => st (xw_a), - => ts (xw_b)
__device__ float g_call_sorted[EE];
__device__ float g_dinv_st[NN], g_dinv_ts[NN], g_dinv_all[NN];
__device__ int   g_flags[2];          // [0]=saw_float_bits, [1]=saw_byte_layout

// ---------------- helpers ----------------
__device__ __forceinline__ int edge_reversed(const void* m, int e) {
    if (g_flags[1]) return ((const unsigned char*)m)[e] != 0;
    if (g_flags[0]) return ((const float*)m)[e] != 0.0f;
    return ((const int*)m)[e] != 0;
}

__device__ __forceinline__ uint32_t f2tf32(float f) {
    uint32_t r;
    asm("cvt.rna.tf32.f32 %0, %1;" : "=r"(r) : "f"(f));
    return r;
}

__device__ __forceinline__ void mma_tf32(float* c, const uint32_t* a, const uint32_t* b) {
    asm volatile("mma.sync.aligned.m16n8k8.row.col.f32.tf32.tf32.f32 "
                 "{%0,%1,%2,%3}, {%4,%5,%6,%7}, {%8,%9}, {%0,%1,%2,%3};"
                 : "+f"(c[0]), "+f"(c[1]), "+f"(c[2]), "+f"(c[3])
                 : "r"(a[0]), "r"(a[1]), "r"(a[2]), "r"(a[3]), "r"(b[0]), "r"(b[1]));
}

// ---------------- prep: zero degree arrays + probe is_reversed layout ----------------
__global__ void k_prep(const unsigned int* __restrict__ m) {
    int i = blockIdx.x * blockDim.x + threadIdx.x;
    if (i < NN) { g_degi_st[i] = 0; g_degi_ts[i] = 0; }
    if (i < 2) g_flags[i] = 0;
    unsigned int sawF = 0, sawB = 0;
    if (i < 200000) {
        unsigned int w = m[i];
        if (w > 1u) { if (w == 0x3F800000u) sawF = 1; else sawB = 1; }
    }
    sawF = __any_sync(0xFFFFFFFF, sawF);
    sawB = __any_sync(0xFFFFFFFF, sawB);
    if ((threadIdx.x & 31) == 0) {
        if (sawF) atomicOr(&g_flags[0], 1);
        if (sawB) atomicOr(&g_flags[1], 1);
    }
}

// ---------------- degree histogram ----------------
__global__ void k_hist(const int* __restrict__ dst, const void* __restrict__ mrev) {
    int e = blockIdx.x * blockDim.x + threadIdx.x;
    if (e >= EE) return;
    int d = dst[e];
    if (edge_reversed(mrev, e)) atomicAdd(&g_degi_ts[d], 1);
    else                        atomicAdd(&g_degi_st[d], 1);
}

__global__ void k_dinv() {
    int n = blockIdx.x * blockDim.x + threadIdx.x;
    if (n >= NN) return;
    int ids = g_degi_st[n], idt = g_degi_ts[n];
    float ds = (float)ids, dt = (float)idt;
    g_degtot[n] = ids + idt;
    g_dinv_st[n]  = rsqrtf(ds + 1.f);
    g_dinv_ts[n]  = rsqrtf(dt + 1.f);
    g_dinv_all[n] = rsqrtf(ds + dt + 1.f);
}

// ---------------- two-level exclusive scan of degtot -> rowstart ----------------
__global__ __launch_bounds__(1024)
void k_scan1() {
    int b = blockIdx.x, t = threadIdx.x;
    int i = b * 1024 + t;
    int v = (i < NN) ? g_degtot[i] : 0;
    int lane = t & 31, wid = t >> 5;
    int x = v;
#pragma unroll
    for (int o = 1; o < 32; o <<= 1) {
        int u = __shfl_up_sync(0xFFFFFFFF, x, o);
        if (lane >= o) x += u;
    }
    __shared__ int ws[32];
    if (lane == 31) ws[wid] = x;
    __syncthreads();
    if (wid == 0) {
        int s = ws[lane];
#pragma unroll
        for (int o = 1; o < 32; o <<= 1) {
            int u = __shfl_up_sync(0xFFFFFFFF, s, o);
            if (lane >= o) s += u;
        }
        ws[lane] = s;
    }
    __syncthreads();
    int incl = x + (wid > 0 ? ws[wid - 1] : 0);
    if (i < NN) g_rowstart[i] = incl - v;
    if (t == 1023) g_bsum[b] = incl;
}

__global__ __launch_bounds__(64)
void k_scan2() {
    int t = threadIdx.x;
    int v = (t < SCAN_B) ? g_bsum[t] : 0;
    int lane = t & 31, wid = t >> 5;
    int x = v;
#pragma unroll
    for (int o = 1; o < 32; o <<= 1) {
        int u = __shfl_up_sync(0xFFFFFFFF, x, o);
        if (lane >= o) x += u;
    }
    __shared__ int w0;
    if (wid == 0 && lane == 31) w0 = x;
    __syncthreads();
    int incl = x + (wid == 1 ? w0 : 0);
    if (t < SCAN_B) g_boff[t] = incl - v;
}

__global__ __launch_bounds__(1024)
void k_scan3() {
    int b = blockIdx.x, t = threadIdx.x;
    int i = b * 1024 + t;
    if (i < NN) {
        int r = g_rowstart[i] + g_boff[b];
        g_rowstart[i] = r;
        g_cursor[i] = r;
    }
    if (i == 0) g_rowstart[NN] = EE;
}

// ---------------- fill CSR buckets ----------------
__global__ void k_fill(const int* __restrict__ src, const int* __restrict__ dst,
                       const void* __restrict__ mrev) {
    int e = blockIdx.x * blockDim.x + threadIdx.x;
    if (e >= EE) return;
    int s = src[e], d = dst[e];
    int rev = edge_reversed(mrev, e);
    int pos = atomicAdd(&g_cursor[d], 1);
    float c = rev ? (g_dinv_ts[s] * g_dinv_ts[d]) : (g_dinv_st[s] * g_dinv_st[d]);
    g_src_sorted[pos]  = s;
    g_cdir_sorted[pos] = rev ? -c : c;
    g_call_sorted[pos] = g_dinv_all[s] * g_dinv_all[d];
}

// ---------------- tensor-core GEMM: C[M,128] = A[M,K] @ [Wa | Wb] -------------
// tf32 mma.m16n8k8 with 2-term split (fp32-level precision, ~2^-22 per elem).
// 8 warps = 4(m) x 2(n); warp tile 32x64 = 2 m-tiles x 8 n-tiles.
__global__ __launch_bounds__(256, 2)
void k_gemm_tc(const float* __restrict__ Aparam, int M, int K,
               const float* __restrict__ Wa, const float* __restrict__ Wb,
               int asel) {
    const float* A = asel ? g_h : Aparam;
    __shared__ float sA[2][128 * 8];
    __shared__ float sB[2][8 * BSTRIDE];
    int tid = threadIdx.x;
    int wid = tid >> 5, lane = tid & 31;
    int wm = wid >> 1, wn = wid & 1;
    int tq = lane >> 2, tr = lane & 3;
    int bm = blockIdx.x * 128;

    // gmem->smem mapping
    int ar = tid >> 1, ac = (tid & 1) * 4;   // A: row 0..127, col-group 0/4
    int bkrow = tid >> 5;                    // B: k-row 0..7
    int bcol = lane * 4;                     // B: col 0..124

    int agrow = bm + ar;
    bool arow_ok = agrow < M;
    const float* Abase = A + (size_t)agrow * K + ac;

    float acc[2][8][4];
#pragma unroll
    for (int mt = 0; mt < 2; mt++)
#pragma unroll
        for (int nt = 0; nt < 8; nt++)
#pragma unroll
            for (int j = 0; j < 4; j++) acc[mt][nt][j] = 0.f;

    int nch = (K + 7) / 8;

    // prologue: chunk 0 -> buf 0
    {
        float4 av = make_float4(0.f, 0.f, 0.f, 0.f);
        if (arow_ok && ac < K) av = *(const float4*)(Abase);
        *(float4*)&sA[0][ar * 8 + ac] = av;
        float4 bv = make_float4(0.f, 0.f, 0.f, 0.f);
        if (bkrow < K) {
            if (lane < 16) bv = *(const float4*)(Wa + bkrow * 64 + bcol);
            else           bv = *(const float4*)(Wb + bkrow * 64 + (bcol - 64));
        }
        *(float4*)&sB[0][bkrow * BSTRIDE + bcol] = bv;
    }
    __syncthreads();

    int buf = 0;
    for (int ch = 0; ch < nch; ch++) {
        int k0n = (ch + 1) * 8;
        float4 av2 = make_float4(0.f, 0.f, 0.f, 0.f);
        float4 bv2 = make_float4(0.f, 0.f, 0.f, 0.f);
        if (ch + 1 < nch) {
            if (arow_ok && (k0n + ac) < K) av2 = *(const float4*)(Abase + k0n);
            int bk = k0n + bkrow;
            if (bk < K) {
                if (lane < 16) bv2 = *(const float4*)(Wa + bk * 64 + bcol);
                else           bv2 = *(const float4*)(Wb + bk * 64 + (bcol - 64));
            }
        }

        // A fragments (2 m-tiles), split hi/lo
        uint32_t ahi[2][4], alo[2][4];
#pragma unroll
        for (int mt = 0; mt < 2; mt++) {
            int rb = wm * 32 + mt * 16;
#pragma unroll
            for (int j = 0; j < 4; j++) {
                int row = rb + tq + (j & 1) * 8;
                int col = tr + (j >> 1) * 4;
                float f = sA[buf][row * 8 + col];
                uint32_t hi = f2tf32(f);
                ahi[mt][j] = hi;
                alo[mt][j] = f2tf32(f - __uint_as_float(hi));
            }
        }

#pragma unroll
        for (int nt = 0; nt < 8; nt++) {
            int cb = wn * 64 + nt * 8 + tq;
            float f0 = sB[buf][tr * BSTRIDE + cb];
            float f1 = sB[buf][(tr + 4) * BSTRIDE + cb];
            uint32_t bhi[2], blo[2];
            bhi[0] = f2tf32(f0); blo[0] = f2tf32(f0 - __uint_as_float(bhi[0]));
            bhi[1] = f2tf32(f1); blo[1] = f2tf32(f1 - __uint_as_float(bhi[1]));
#pragma unroll
            for (int mt = 0; mt < 2; mt++) {
                mma_tf32(acc[mt][nt], ahi[mt], bhi);
                mma_tf32(acc[mt][nt], ahi[mt], blo);
                mma_tf32(acc[mt][nt], alo[mt], bhi);
            }
        }

        if (ch + 1 < nch) {
            int nb = buf ^ 1;
            *(float4*)&sA[nb][ar * 8 + ac] = av2;
            *(float4*)&sB[nb][bkrow * BSTRIDE + bcol] = bv2;
            __syncthreads();
            buf = nb;
        }
    }

    // store: wn==0 -> g_xw_a cols 0..63 ; wn==1 -> g_xw_b cols 0..63
    float* C = wn ? g_xw_b : g_xw_a;
#pragma unroll
    for (int mt = 0; mt < 2; mt++) {
        int row0 = bm + wm * 32 + mt * 16 + tq;
#pragma unroll
        for (int nt = 0; nt < 8; nt++) {
            int col = nt * 8 + tr * 2;
            if (row0 < M)
                *(float2*)(C + (size_t)row0 * 64 + col) = make_float2(acc[mt][nt][0], acc[mt][nt][1]);
            if (row0 + 8 < M)
                *(float2*)(C + (size_t)(row0 + 8) * 64 + col) = make_float2(acc[mt][nt][2], acc[mt][nt][3]);
        }
    }
}

// ---------------- gather aggregation + combine + relu -> h ----------------
__global__ __launch_bounds__(64)
void k_gather64(const float* __restrict__ b_st, const float* __restrict__ b_ts) {
    int n = blockIdx.x;
    int c = threadIdx.x;
    int rs = g_rowstart[n], re = g_rowstart[n + 1];
    float acc_a = 0.f, acc_b = 0.f;
    int i = rs;
    for (; i + 3 < re; i += 4) {
        int   s0 = g_src_sorted[i],   s1 = g_src_sorted[i+1];
        int   s2 = g_src_sorted[i+2], s3 = g_src_sorted[i+3];
        float c0 = g_cdir_sorted[i],   c1 = g_cdir_sorted[i+1];
        float c2 = g_cdir_sorted[i+2], c3 = g_cdir_sorted[i+3];
        float v0 = (c0 >= 0.f) ? g_xw_a[s0 * 64 + c] : g_xw_b[s0 * 64 + c];
        float v1 = (c1 >= 0.f) ? g_xw_a[s1 * 64 + c] : g_xw_b[s1 * 64 + c];
        float v2 = (c2 >= 0.f) ? g_xw_a[s2 * 64 + c] : g_xw_b[s2 * 64 + c];
        float v3 = (c3 >= 0.f) ? g_xw_a[s3 * 64 + c] : g_xw_b[s3 * 64 + c];
        if (c0 >= 0.f) acc_a = fmaf(c0, v0, acc_a); else acc_b = fmaf(-c0, v0, acc_b);
        if (c1 >= 0.f) acc_a = fmaf(c1, v1, acc_a); else acc_b = fmaf(-c1, v1, acc_b);
        if (c2 >= 0.f) acc_a = fmaf(c2, v2, acc_a); else acc_b = fmaf(-c2, v2, acc_b);
        if (c3 >= 0.f) acc_a = fmaf(c3, v3, acc_a); else acc_b = fmaf(-c3, v3, acc_b);
    }
    for (; i < re; i++) {
        int   s0 = g_src_sorted[i];
        float c0 = g_cdir_sorted[i];
        float v0 = (c0 >= 0.f) ? g_xw_a[s0 * 64 + c] : g_xw_b[s0 * 64 + c];
        if (c0 >= 0.f) acc_a = fmaf(c0, v0, acc_a); else acc_b = fmaf(-c0, v0, acc_b);
    }
    float da = g_dinv_st[n], db = g_dinv_ts[n];
    float va = acc_a + g_xw_a[n * 64 + c] * da * da + b_st[c];
    float vb = acc_b + g_xw_b[n * 64 + c] * db * db + b_ts[c];
    g_h[n * 128 + c]      = fmaxf(va, 0.f);
    g_h[n * 128 + 64 + c] = fmaxf(vb, 0.f);
}

// ---------------- last layer: xw_l = h @ W_last ----------------
__global__ void k_gemm16(const float* __restrict__ Wl) {
    __shared__ float Ws[128 * 16];
    for (int i = threadIdx.x; i < 128 * 16; i += blockDim.x) Ws[i] = Wl[i];
    __syncthreads();
    int idx = blockIdx.x * blockDim.x + threadIdx.x;
    int n = idx >> 4;
    int j = idx & 15;
    if (n >= NN) return;
    const float* hr = g_h + (size_t)n * 128;
    float acc = 0.f;
#pragma unroll
    for (int k = 0; k < 128; k++) acc = fmaf(hr[k], Ws[k * 16 + j], acc);
    g_xw_l[n * 16 + j] = acc;
}

// ---------------- final gather + combine + log_softmax -> out ----------------
__global__ __launch_bounds__(128)
void k_gather16_final(const float* __restrict__ b_last, float* __restrict__ out) {
    int lid = threadIdx.x & 15;
    int grp = threadIdx.x >> 4;
    int n = blockIdx.x * 8 + grp;
    int rs = g_rowstart[n], re = g_rowstart[n + 1];
    float acc = 0.f;
    int i = rs;
    for (; i + 1 < re; i += 2) {
        int   s0 = g_src_sorted[i],  s1 = g_src_sorted[i+1];
        float f0 = g_call_sorted[i], f1 = g_call_sorted[i+1];
        acc = fmaf(f0, g_xw_l[s0 * 16 + lid], acc);
        acc = fmaf(f1, g_xw_l[s1 * 16 + lid], acc);
    }
    if (i < re) acc = fmaf(g_call_sorted[i], g_xw_l[g_src_sorted[i] * 16 + lid], acc);
    float dinv = g_dinv_all[n];
    float v = acc + g_xw_l[n * 16 + lid] * dinv * dinv + b_last[lid];
    float m = v;
#pragma unroll
    for (int o = 8; o > 0; o >>= 1) m = fmaxf(m, __shfl_xor_sync(0xFFFFFFFF, m, o, 16));
    float ex = expf(v - m);
    float ssum = ex;
#pragma unroll
    for (int o = 8; o > 0; o >>= 1) ssum += __shfl_xor_sync(0xFFFFFFFF, ssum, o, 16);
    out[n * 16 + lid] = v - (logf(ssum) + m);
}

// ---------------- launch ----------------
extern "C" void kernel_launch(void* const* d_in, const int* in_sizes, int n_in,
                              void* d_out, int out_size) {
    const float* x      = (const float*)d_in[0];
    const int*   ei     = (const int*)d_in[1];
    const void*  mrev   = d_in[2];
    const float* W_st0  = (const float*)d_in[3];
    const float* b_st0  = (const float*)d_in[4];
    const float* W_ts0  = (const float*)d_in[5];
    const float* b_ts0  = (const float*)d_in[6];
    const float* W_st1  = (const float*)d_in[7];
    const float* b_st1  = (const float*)d_in[8];
    const float* W_ts1  = (const float*)d_in[9];
    const float* b_ts1  = (const float*)d_in[10];
    const float* W_last = (const float*)d_in[11];
    const float* b_last = (const float*)d_in[12];
    float* out = (float*)d_out;

    const int* srcp = ei;
    const int* dstp = ei + EE;
    const int TB = 256;
    const int GEMM_BLOCKS = (NN + 127) / 128;

    // launches 0-2
    k_prep<<<(200000 + TB - 1) / TB, TB>>>((const unsigned int*)mrev);
    k_hist<<<(EE + TB - 1) / TB, TB>>>(dstp, mrev);
    k_dinv<<<(NN + TB - 1) / TB, TB>>>();

    // launch 3: tensor-core GEMM L0 (profiled slot)
    k_gemm_tc<<<GEMM_BLOCKS, 256>>>(x, NN, FIN, W_st0, W_ts0, 0);

    // CSR build
    k_scan1<<<SCAN_B, 1024>>>();
    k_scan2<<<1, 64>>>();
    k_scan3<<<SCAN_B, 1024>>>();
    k_fill<<<(EE + TB - 1) / TB, TB>>>(srcp, dstp, mrev);

    // layer 0 aggregation
    k_gather64<<<NN, 64>>>(b_st0, b_ts0);

    // layer 1
    k_gemm_tc<<<GEMM_BLOCKS, 256>>>(nullptr, NN, 2 * HH, W_st1, W_ts1, 1);
    k_gather64<<<NN, 64>>>(b_st1, b_ts1);

    // last layer
    k_gemm16<<<(NN * 16) / TB, TB>>>(W_last);
    k_gather16_final<<<NN / 8, 128>>>(b_last, out);
}